// round 13
// baseline (speedup 1.0000x reference)
#include <cuda_runtime.h>

#define N_VERTICES 1000000
#define N_EDGES    16000000
#define VPB        1024          // vertices per finalize block

// Scratch accumulator. Zero-initialized at module load; finalize_kernel
// resets it after consuming it, so every graph replay starts clean.
__device__ float g_cbar[N_VERTICES];

// Scatter: 16 edges per thread (4x int4 index loads + 8x float4 edge_attr
// loads + 16 spread-address fp32 REDs). Lane count (16M) is pinned at the
// per-SM LSU spread-RED floor; deeper batches only shave non-RED overhead.
// 1M threads = 128 x 7813 (guarded).
__global__ void __launch_bounds__(128, 8)
scatter_kernel(const int* __restrict__ src_idx,
               const float* __restrict__ edge_attr) {
    unsigned t = blockIdx.x * blockDim.x + threadIdx.x;   // [0, 1,000,064)
    if (t >= N_EDGES / 16) return;
    const int4*   idx4 = (const int4*)src_idx;
    const float4* ea4  = (const float4*)edge_attr;

    int4   ia = idx4[4u * t];
    int4   ib = idx4[4u * t + 1u];
    int4   ic = idx4[4u * t + 2u];
    int4   id = idx4[4u * t + 3u];
    float4 e0 = ea4[8u * t];
    float4 e1 = ea4[8u * t + 1u];
    float4 e2 = ea4[8u * t + 2u];
    float4 e3 = ea4[8u * t + 3u];
    float4 e4 = ea4[8u * t + 4u];
    float4 e5 = ea4[8u * t + 5u];
    float4 e6 = ea4[8u * t + 6u];
    float4 e7 = ea4[8u * t + 7u];

    atomicAdd(&g_cbar[ia.x], e0.y);
    atomicAdd(&g_cbar[ia.y], e0.w);
    atomicAdd(&g_cbar[ia.z], e1.y);
    atomicAdd(&g_cbar[ia.w], e1.w);
    atomicAdd(&g_cbar[ib.x], e2.y);
    atomicAdd(&g_cbar[ib.y], e2.w);
    atomicAdd(&g_cbar[ib.z], e3.y);
    atomicAdd(&g_cbar[ib.w], e3.w);
    atomicAdd(&g_cbar[ic.x], e4.y);
    atomicAdd(&g_cbar[ic.y], e4.w);
    atomicAdd(&g_cbar[ic.z], e5.y);
    atomicAdd(&g_cbar[ic.w], e5.w);
    atomicAdd(&g_cbar[id.x], e6.y);
    atomicAdd(&g_cbar[id.y], e6.w);
    atomicAdd(&g_cbar[id.z], e7.y);
    atomicAdd(&g_cbar[id.w], e7.w);
}

// Finalize: smem-staged for fully coalesced global traffic (unchanged, R12).
__global__ void __launch_bounds__(128, 8)
finalize_kernel(const float* __restrict__ vertex_attr,
                float* __restrict__ out) {
    __shared__ float srow[VPB * 3];          // 12 KB
    unsigned base = blockIdx.x * VPB;
    unsigned rem  = N_VERTICES - base;
    if (rem > VPB) rem = VPB;

#pragma unroll
    for (int k = 0; k < VPB / 128; k++) {
        unsigned l = threadIdx.x + 128u * k;     // local vertex
        if (l < rem) {
            unsigned v = base + l;
            float2 bx = ((const float2*)vertex_attr)[v];
            float  c  = g_cbar[v];
            g_cbar[v] = 0.0f;
            srow[3u * l + 0u] = bx.x;
            srow[3u * l + 1u] = bx.y;
            srow[3u * l + 2u] = bx.x - c;
        }
    }
    __syncthreads();

    const float4* s4 = (const float4*)srow;
    float4* o4 = (float4*)(out + 3ull * base);
    unsigned n4 = rem * 3u / 4u;                 // 768 (full) / 432 (tail)
#pragma unroll
    for (unsigned j = threadIdx.x; j < n4; j += 128u)
        o4[j] = s4[j];
}

extern "C" void kernel_launch(void* const* d_in, const int* in_sizes, int n_in,
                              void* d_out, int out_size) {
    // Inputs (JAX x64 disabled => "int64" arrays are int32 on device):
    // 0: vertex_attr (1M x 2) f32, 1: edgeij_pair (2 x 16M) i32 (row0 = src),
    // 2: edge_attr (16M x 2) f32, 3: g (unused), 4: batch (unused)
    const float* vertex_attr = (const float*)d_in[0];
    const int*   edge_src    = (const int*)d_in[1];
    const float* edge_attr   = (const float*)d_in[2];
    float*       out         = (float*)d_out;

    // Scatter: 16M edges / 16 = 1M threads = 128 x 7813 (guarded).
    {
        const int threads = 128;
        const int blocks  = (N_EDGES / 16 + threads - 1) / threads;  // 7813
        scatter_kernel<<<blocks, threads>>>(edge_src, edge_attr);
    }
    // Finalize: 977 blocks x 128 threads, 1024 vertices per block.
    {
        const int blocks = (N_VERTICES + VPB - 1) / VPB;  // 977
        finalize_kernel<<<blocks, 128>>>(vertex_attr, out);
    }
}

// round 15
// speedup vs baseline: 1.1838x; 1.1838x over previous
#include <cuda_runtime.h>

#define N_VERTICES 1000000
#define N_EDGES    16000000
#define VPB        1024          // vertices per finalize block

// Scratch accumulator. Zero-initialized at module load; finalize_kernel
// resets it after consuming it, so every graph replay starts clean.
__device__ float g_cbar[N_VERTICES];

// Scatter: 8 edges per thread (2x int4 index loads + 4x float4 edge_attr
// loads + 8 spread-address fp32 REDs). Sits at the per-SM LSU spread-RED
// lane floor (~1.29 cyc/lane); 8/thread with 2M threads is the measured
// sweet spot (4/thread: +2us overhead; 16/thread: +11us, RED tail starves
// the LSU of independent warps). 128 x 15625 = exactly 2M threads.
__global__ void __launch_bounds__(128, 16)
scatter_kernel(const int* __restrict__ src_idx,
               const float* __restrict__ edge_attr) {
    unsigned t = blockIdx.x * blockDim.x + threadIdx.x;   // [0, 2,000,000)
    const int4*   idx4 = (const int4*)src_idx;
    const float4* ea4  = (const float4*)edge_attr;

    int4   ia = idx4[2u * t];
    int4   ib = idx4[2u * t + 1u];
    float4 e0 = ea4[4u * t];
    float4 e1 = ea4[4u * t + 1u];
    float4 e2 = ea4[4u * t + 2u];
    float4 e3 = ea4[4u * t + 3u];

    atomicAdd(&g_cbar[ia.x], e0.y);
    atomicAdd(&g_cbar[ia.y], e0.w);
    atomicAdd(&g_cbar[ia.z], e1.y);
    atomicAdd(&g_cbar[ia.w], e1.w);
    atomicAdd(&g_cbar[ib.x], e2.y);
    atomicAdd(&g_cbar[ib.y], e2.w);
    atomicAdd(&g_cbar[ib.z], e3.y);
    atomicAdd(&g_cbar[ib.w], e3.w);
}

// Finalize: smem-staged for fully coalesced global traffic.
// Phase 1 (lane-strided): float2 va loads (256B/warp/instr), scalar cbar
// load+reset (128B/warp/instr), rows composed into smem (stride-3-word
// writes, conflict-free since gcd(3,32)=1).
// Phase 2: flush the 12KB row buffer as lane-contiguous float4 stores
// (every STG.128 = one 4-line coalesced wavefront).
// Tail block (576 vertices) still has float counts divisible by 4.
__global__ void __launch_bounds__(128, 8)
finalize_kernel(const float* __restrict__ vertex_attr,
                float* __restrict__ out) {
    __shared__ float srow[VPB * 3];          // 12 KB
    unsigned base = blockIdx.x * VPB;
    unsigned rem  = N_VERTICES - base;
    if (rem > VPB) rem = VPB;

#pragma unroll
    for (int k = 0; k < VPB / 128; k++) {
        unsigned l = threadIdx.x + 128u * k;     // local vertex
        if (l < rem) {
            unsigned v = base + l;
            float2 bx = ((const float2*)vertex_attr)[v];
            float  c  = g_cbar[v];
            g_cbar[v] = 0.0f;
            srow[3u * l + 0u] = bx.x;
            srow[3u * l + 1u] = bx.y;
            srow[3u * l + 2u] = bx.x - c;
        }
    }
    __syncthreads();

    const float4* s4 = (const float4*)srow;
    float4* o4 = (float4*)(out + 3ull * base);
    unsigned n4 = rem * 3u / 4u;                 // 768 (full) / 432 (tail)
#pragma unroll
    for (unsigned j = threadIdx.x; j < n4; j += 128u)
        o4[j] = s4[j];
}

extern "C" void kernel_launch(void* const* d_in, const int* in_sizes, int n_in,
                              void* d_out, int out_size) {
    // Inputs (JAX x64 disabled => "int64" arrays are int32 on device):
    // 0: vertex_attr (1M x 2) f32, 1: edgeij_pair (2 x 16M) i32 (row0 = src),
    // 2: edge_attr (16M x 2) f32, 3: g (unused), 4: batch (unused)
    const float* vertex_attr = (const float*)d_in[0];
    const int*   edge_src    = (const int*)d_in[1];
    const float* edge_attr   = (const float*)d_in[2];
    float*       out         = (float*)d_out;

    // Scatter: 16M edges / 8 = 2M threads = 128 x 15625 exact.
    {
        const int threads = 128;
        const int blocks  = (N_EDGES / 8) / threads;  // 15625
        scatter_kernel<<<blocks, threads>>>(edge_src, edge_attr);
    }
    // Finalize: 977 blocks x 128 threads, 1024 vertices per block.
    {
        const int blocks = (N_VERTICES + VPB - 1) / VPB;  // 977
        finalize_kernel<<<blocks, 128>>>(vertex_attr, out);
    }
}